// round 5
// baseline (speedup 1.0000x reference)
#include <cuda_runtime.h>

// Problem constants
#define NROW 16384      // B
#define MDIM 4096       // M*DV
#define NSLOT 64        // M
#define DVC 64
#define DKC 64
#define DQAC 128

// 256 MB scratch for memory_pre (uninitialized __device__ global = allowed scratch)
__device__ float g_mpre[(size_t)NROW * MDIM];

__device__ __forceinline__ float sigf(float x) { return 1.0f / (1.0f + __expf(-x)); }

// 64x64 register-tiled GEMM fragment: acc[4][4] += sa[r0..r0+3][k] * sb[k][4tx..4tx+3]
template <int NK4>
__device__ __forceinline__ void gemm_acc(const float* __restrict__ sa, int lda,
                                         const float* __restrict__ sb, int ldb,
                                         int r0, int tx, float acc[4][4]) {
#pragma unroll 2
    for (int k4 = 0; k4 < NK4; k4++) {
        float ar[4][4];
#pragma unroll
        for (int i = 0; i < 4; i++) {
            float4 a = *(const float4*)(sa + (r0 + i) * lda + k4 * 4);
            ar[i][0] = a.x; ar[i][1] = a.y; ar[i][2] = a.z; ar[i][3] = a.w;
        }
#pragma unroll
        for (int kk = 0; kk < 4; kk++) {
            float4 b = *(const float4*)(sb + (k4 * 4 + kk) * ldb + tx * 4);
#pragma unroll
            for (int i = 0; i < 4; i++) {
                acc[i][0] = fmaf(ar[i][kk], b.x, acc[i][0]);
                acc[i][1] = fmaf(ar[i][kk], b.y, acc[i][1]);
                acc[i][2] = fmaf(ar[i][kk], b.z, acc[i][2]);
                acc[i][3] = fmaf(ar[i][kk], b.w, acc[i][3]);
            }
        }
    }
}

// Shared memory layout (floats):
//   s_c0 : [64][132]  content0 block (persistent after phase 0)       8448
//   s_w  : 13056 floats staging region (Wc0 / Wm1 / W-triple / We/Wz/Wza / erase+add+mkT)
//   s_mp : [64][68]   mv chunk / mp chunk / zt / ck / ww              4352
#define SC0LD 132
#define SWLD 68
#define S_W_OFF (64 * 132)
#define S_MP_OFF (S_W_OFF + 13056)
#define SMEM_FLOATS (S_MP_OFF + 64 * 68)   // 25856 floats = 103424 bytes

__global__ void __launch_bounds__(256, 1)
memnet_fused(const float* __restrict__ ck, const float* __restrict__ qa,
             const float* __restrict__ mk, const float* __restrict__ mv,
             const float* __restrict__ We, const float* __restrict__ be,
             const float* __restrict__ Wemv, const float* __restrict__ bemv,
             const float* __restrict__ Wza, const float* __restrict__ bza,
             const float* __restrict__ Wamv, const float* __restrict__ bamv,
             const float* __restrict__ Wc0, const float* __restrict__ bc0,
             const float* __restrict__ Wm1, const float* __restrict__ bm1,
             const float* __restrict__ Wz, const float* __restrict__ bz,
             const float* __restrict__ Wzmv, const float* __restrict__ bzmv,
             float* __restrict__ out)
{
    extern __shared__ float sm[];
    float* s_c0 = sm;
    float* s_w  = sm + S_W_OFF;
    float* s_mp = sm + S_MP_OFF;

    const int tid = threadIdx.x;
    const int tx = tid & 15;
    const int ty = tid >> 4;
    const int r0 = ty * 4;
    const int rb = blockIdx.x * 64;

    // =========== Phase 0: content0 = qa * sigmoid(mem_flat0 @ Wc0 + bc0) ===========
    float acc0[4][8];
#pragma unroll
    for (int i = 0; i < 4; i++)
#pragma unroll
        for (int j = 0; j < 8; j++) acc0[i][j] = 0.0f;

    for (int c = 0; c < 64; c++) {
        // mv chunk (64 rows x 64 cols) -> s_mp
#pragma unroll
        for (int l = 0; l < 4; l++) {
            int idx = tid + l * 256;
            int r = idx >> 4, k4 = idx & 15;
            float4 v = *(const float4*)(mv + (size_t)(rb + r) * MDIM + c * 64 + k4 * 4);
            *(float4*)(s_mp + r * SWLD + k4 * 4) = v;
        }
        // Wc0 chunk (64 k-rows x 128 cols) -> s_w [k][132]
#pragma unroll
        for (int l = 0; l < 8; l++) {
            int idx = tid + l * 256;
            int k = idx >> 5, n4 = idx & 31;
            float4 v = *(const float4*)(Wc0 + (size_t)(c * 64 + k) * DQAC + n4 * 4);
            *(float4*)(s_w + k * SC0LD + n4 * 4) = v;
        }
        __syncthreads();
#pragma unroll 2
        for (int k4 = 0; k4 < 16; k4++) {
            float ar[4][4];
#pragma unroll
            for (int i = 0; i < 4; i++) {
                float4 a = *(const float4*)(s_mp + (r0 + i) * SWLD + k4 * 4);
                ar[i][0] = a.x; ar[i][1] = a.y; ar[i][2] = a.z; ar[i][3] = a.w;
            }
#pragma unroll
            for (int kk = 0; kk < 4; kk++) {
                int k = k4 * 4 + kk;
                float4 b0 = *(const float4*)(s_w + k * SC0LD + tx * 8);
                float4 b1 = *(const float4*)(s_w + k * SC0LD + tx * 8 + 4);
                float bb[8] = {b0.x, b0.y, b0.z, b0.w, b1.x, b1.y, b1.z, b1.w};
#pragma unroll
                for (int i = 0; i < 4; i++)
#pragma unroll
                    for (int j = 0; j < 8; j++)
                        acc0[i][j] = fmaf(ar[i][kk], bb[j], acc0[i][j]);
            }
        }
        __syncthreads();
    }
    // content0 epilogue -> s_c0
    {
        float4 bcl0 = *(const float4*)(bc0 + tx * 8);
        float4 bcl1 = *(const float4*)(bc0 + tx * 8 + 4);
        float bcv[8] = {bcl0.x, bcl0.y, bcl0.z, bcl0.w, bcl1.x, bcl1.y, bcl1.z, bcl1.w};
#pragma unroll
        for (int i = 0; i < 4; i++) {
            int row = rb + r0 + i;
            float4 q0 = *(const float4*)(qa + (size_t)row * DQAC + tx * 8);
            float4 q1 = *(const float4*)(qa + (size_t)row * DQAC + tx * 8 + 4);
            float qv[8] = {q0.x, q0.y, q0.z, q0.w, q1.x, q1.y, q1.z, q1.w};
#pragma unroll
            for (int j = 0; j < 8; j++) {
                s_c0[(r0 + i) * SC0LD + tx * 8 + j] =
                    qv[j] * sigf(acc0[i][j] + bcv[j]);
            }
        }
    }
    // visibility of s_c0 is guaranteed by the sync after the first Wm1 load below

    // =========== Phase 1: gate, memory_pre, and the three K=4096 reductions ===========
    float aE[4][4], aZ[4][4], aA[4][4];
#pragma unroll
    for (int i = 0; i < 4; i++)
#pragma unroll
        for (int j = 0; j < 4; j++) { aE[i][j] = 0.f; aZ[i][j] = 0.f; aA[i][j] = 0.f; }

    for (int c = 0; c < 64; c++) {
        // Wm1 chunk (128 x 64) -> s_w [k][68]
#pragma unroll
        for (int l = 0; l < 8; l++) {
            int idx = tid + l * 256;
            int k = idx >> 4, c4 = idx & 15;
            float4 v = *(const float4*)(Wm1 + (size_t)k * MDIM + c * 64 + c4 * 4);
            *(float4*)(s_w + k * SWLD + c4 * 4) = v;
        }
        __syncthreads();

        // gate GEMM: g = content0 @ Wm1_chunk  (K = 128)
        float g[4][4];
#pragma unroll
        for (int i = 0; i < 4; i++)
#pragma unroll
            for (int j = 0; j < 4; j++) g[i][j] = 0.f;
        gemm_acc<32>(s_c0, SC0LD, s_w, SWLD, r0, tx, g);

        // memory_pre = mv * sigmoid(g + bm1); store to smem + global scratch
        {
            float4 bm = *(const float4*)(bm1 + c * 64 + tx * 4);
#pragma unroll
            for (int i = 0; i < 4; i++) {
                int row = rb + r0 + i;
                float4 v = *(const float4*)(mv + (size_t)row * MDIM + c * 64 + tx * 4);
                float4 mp4;
                mp4.x = v.x * sigf(g[i][0] + bm.x);
                mp4.y = v.y * sigf(g[i][1] + bm.y);
                mp4.z = v.z * sigf(g[i][2] + bm.z);
                mp4.w = v.w * sigf(g[i][3] + bm.w);
                *(float4*)(s_mp + (r0 + i) * SWLD + tx * 4) = mp4;
                *(float4*)(g_mpre + (size_t)row * MDIM + c * 64 + tx * 4) = mp4;
            }
        }
        __syncthreads();

        // load Wemv / Wzmv / Wamv chunks (each 64 x 64) into s_w triple
#pragma unroll
        for (int l = 0; l < 4; l++) {
            int idx = tid + l * 256;
            int k = idx >> 4, d4 = idx & 15;
            size_t gofs = (size_t)(c * 64 + k) * DVC + d4 * 4;
            *(float4*)(s_w + k * SWLD + d4 * 4)        = *(const float4*)(Wemv + gofs);
            *(float4*)(s_w + 4352 + k * SWLD + d4 * 4) = *(const float4*)(Wzmv + gofs);
            *(float4*)(s_w + 8704 + k * SWLD + d4 * 4) = *(const float4*)(Wamv + gofs);
        }
        __syncthreads();

        // accumulate E/Z/A (K = 64 within this chunk)
#pragma unroll 2
        for (int k4 = 0; k4 < 16; k4++) {
            float ar[4][4];
#pragma unroll
            for (int i = 0; i < 4; i++) {
                float4 a = *(const float4*)(s_mp + (r0 + i) * SWLD + k4 * 4);
                ar[i][0] = a.x; ar[i][1] = a.y; ar[i][2] = a.z; ar[i][3] = a.w;
            }
#pragma unroll
            for (int kk = 0; kk < 4; kk++) {
                int k = k4 * 4 + kk;
                float4 bE = *(const float4*)(s_w + k * SWLD + tx * 4);
                float4 bZ = *(const float4*)(s_w + 4352 + k * SWLD + tx * 4);
                float4 bA = *(const float4*)(s_w + 8704 + k * SWLD + tx * 4);
#pragma unroll
                for (int i = 0; i < 4; i++) {
                    float av = ar[i][kk];
                    aE[i][0] = fmaf(av, bE.x, aE[i][0]); aE[i][1] = fmaf(av, bE.y, aE[i][1]);
                    aE[i][2] = fmaf(av, bE.z, aE[i][2]); aE[i][3] = fmaf(av, bE.w, aE[i][3]);
                    aZ[i][0] = fmaf(av, bZ.x, aZ[i][0]); aZ[i][1] = fmaf(av, bZ.y, aZ[i][1]);
                    aZ[i][2] = fmaf(av, bZ.z, aZ[i][2]); aZ[i][3] = fmaf(av, bZ.w, aZ[i][3]);
                    aA[i][0] = fmaf(av, bA.x, aA[i][0]); aA[i][1] = fmaf(av, bA.y, aA[i][1]);
                    aA[i][2] = fmaf(av, bA.z, aA[i][2]); aA[i][3] = fmaf(av, bA.w, aA[i][3]);
                }
            }
        }
        __syncthreads();
    }

    // =========== Epilogue ===========
    // --- erase path: sigmoid(sigmoid(content0@We+be) + sigmoid(E+bemv)) ---
#pragma unroll
    for (int l = 0; l < 8; l++) {
        int idx = tid + l * 256;
        int k = idx >> 4, d4 = idx & 15;
        *(float4*)(s_w + k * SWLD + d4 * 4) = *(const float4*)(We + (size_t)k * DVC + d4 * 4);
    }
    __syncthreads();
    float qe[4][4];
#pragma unroll
    for (int i = 0; i < 4; i++)
#pragma unroll
        for (int j = 0; j < 4; j++) qe[i][j] = 0.f;
    gemm_acc<32>(s_c0, SC0LD, s_w, SWLD, r0, tx, qe);

    float er[4][4];
    {
        float4 b1v = *(const float4*)(be + tx * 4);
        float4 b2v = *(const float4*)(bemv + tx * 4);
        float b1a[4] = {b1v.x, b1v.y, b1v.z, b1v.w};
        float b2a[4] = {b2v.x, b2v.y, b2v.z, b2v.w};
#pragma unroll
        for (int i = 0; i < 4; i++)
#pragma unroll
            for (int j = 0; j < 4; j++)
                er[i][j] = sigf(sigf(qe[i][j] + b1a[j]) + sigf(aE[i][j] + b2a[j]));
    }
    __syncthreads();

    // --- zt path: sigmoid(content0@Wz + bz + Z + bzmv) ---
#pragma unroll
    for (int l = 0; l < 8; l++) {
        int idx = tid + l * 256;
        int k = idx >> 4, d4 = idx & 15;
        *(float4*)(s_w + k * SWLD + d4 * 4) = *(const float4*)(Wz + (size_t)k * DVC + d4 * 4);
    }
    __syncthreads();
    float qz[4][4];
#pragma unroll
    for (int i = 0; i < 4; i++)
#pragma unroll
        for (int j = 0; j < 4; j++) qz[i][j] = 0.f;
    gemm_acc<32>(s_c0, SC0LD, s_w, SWLD, r0, tx, qz);
    {
        float4 b1v = *(const float4*)(bz + tx * 4);
        float4 b2v = *(const float4*)(bzmv + tx * 4);
        float b1a[4] = {b1v.x, b1v.y, b1v.z, b1v.w};
        float b2a[4] = {b2v.x, b2v.y, b2v.z, b2v.w};
#pragma unroll
        for (int i = 0; i < 4; i++) {
            float4 zt4;
            zt4.x = sigf(qz[i][0] + b1a[0] + aZ[i][0] + b2a[0]);
            zt4.y = sigf(qz[i][1] + b1a[1] + aZ[i][1] + b2a[1]);
            zt4.z = sigf(qz[i][2] + b1a[2] + aZ[i][2] + b2a[2]);
            zt4.w = sigf(qz[i][3] + b1a[3] + aZ[i][3] + b2a[3]);
            *(float4*)(s_mp + (r0 + i) * SWLD + tx * 4) = zt4;   // zt -> s_mp
        }
    }
    __syncthreads();

    // --- add path: tanh(tanh(zt@Wza+bza) + tanh(A+bamv)) ---
#pragma unroll
    for (int l = 0; l < 4; l++) {
        int idx = tid + l * 256;
        int k = idx >> 4, d4 = idx & 15;
        *(float4*)(s_w + k * SWLD + d4 * 4) = *(const float4*)(Wza + (size_t)k * DVC + d4 * 4);
    }
    __syncthreads();
    float za[4][4];
#pragma unroll
    for (int i = 0; i < 4; i++)
#pragma unroll
        for (int j = 0; j < 4; j++) za[i][j] = 0.f;
    gemm_acc<16>(s_mp, SWLD, s_w, SWLD, r0, tx, za);

    float ad[4][4];
    {
        float4 b1v = *(const float4*)(bza + tx * 4);
        float4 b2v = *(const float4*)(bamv + tx * 4);
        float b1a[4] = {b1v.x, b1v.y, b1v.z, b1v.w};
        float b2a[4] = {b2v.x, b2v.y, b2v.z, b2v.w};
#pragma unroll
        for (int i = 0; i < 4; i++)
#pragma unroll
            for (int j = 0; j < 4; j++)
                ad[i][j] = tanhf(tanhf(za[i][j] + b1a[j]) + tanhf(aA[i][j] + b2a[j]));
    }
    __syncthreads();

    // stash erase/add in s_w; load mk (transposed) and ck for write-weight softmax
#pragma unroll
    for (int i = 0; i < 4; i++) {
        float4 e4 = {er[i][0], er[i][1], er[i][2], er[i][3]};
        float4 a4 = {ad[i][0], ad[i][1], ad[i][2], ad[i][3]};
        *(float4*)(s_w + (r0 + i) * SWLD + tx * 4)        = e4;
        *(float4*)(s_w + 4352 + (r0 + i) * SWLD + tx * 4) = a4;
    }
#pragma unroll
    for (int l = 0; l < 4; l++) {
        int idx = tid + l * 256;
        int m = idx >> 4, k4 = idx & 15;
        float4 v = *(const float4*)(mk + (size_t)m * DKC + k4 * 4);
        s_w[8704 + (k4 * 4 + 0) * SWLD + m] = v.x;
        s_w[8704 + (k4 * 4 + 1) * SWLD + m] = v.y;
        s_w[8704 + (k4 * 4 + 2) * SWLD + m] = v.z;
        s_w[8704 + (k4 * 4 + 3) * SWLD + m] = v.w;
        // ck block -> s_mp
        *(float4*)(s_mp + m * SWLD + k4 * 4) =
            *(const float4*)(ck + (size_t)(rb + m) * DKC + k4 * 4);
    }
    __syncthreads();

    // logits = ck @ mk^T (K = 64), softmax over the 64 slots (spread across tx*4+j)
    float lg[4][4];
#pragma unroll
    for (int i = 0; i < 4; i++)
#pragma unroll
        for (int j = 0; j < 4; j++) lg[i][j] = 0.f;
    gemm_acc<16>(s_mp, SWLD, s_w + 8704, SWLD, r0, tx, lg);

    float wwv[4][4];
#pragma unroll
    for (int i = 0; i < 4; i++) {
        float mmax = fmaxf(fmaxf(lg[i][0], lg[i][1]), fmaxf(lg[i][2], lg[i][3]));
#pragma unroll
        for (int s = 1; s < 16; s <<= 1)
            mmax = fmaxf(mmax, __shfl_xor_sync(0xffffffffu, mmax, s));
        float e0 = __expf(lg[i][0] - mmax);
        float e1 = __expf(lg[i][1] - mmax);
        float e2 = __expf(lg[i][2] - mmax);
        float e3 = __expf(lg[i][3] - mmax);
        float ssum = e0 + e1 + e2 + e3;
#pragma unroll
        for (int s = 1; s < 16; s <<= 1)
            ssum += __shfl_xor_sync(0xffffffffu, ssum, s);
        float inv = 1.0f / ssum;
        wwv[i][0] = e0 * inv; wwv[i][1] = e1 * inv;
        wwv[i][2] = e2 * inv; wwv[i][3] = e3 * inv;
    }
    __syncthreads();
#pragma unroll
    for (int i = 0; i < 4; i++) {
        float4 w4 = {wwv[i][0], wwv[i][1], wwv[i][2], wwv[i][3]};
        *(float4*)(s_mp + (r0 + i) * SWLD + tx * 4) = w4;   // ww -> s_mp
    }
    __syncthreads();

    // =========== Final pass: new_memory = mp * (1 - w*erase) + w*add ===========
    for (int c = 0; c < 64; c++) {
#pragma unroll
        for (int i = 0; i < 4; i++) {
            int r = r0 + i;
            int row = rb + r;
            float w = s_mp[r * SWLD + c];
            float4 mp4 = *(const float4*)(g_mpre + (size_t)row * MDIM + c * 64 + tx * 4);
            float4 e4  = *(const float4*)(s_w + r * SWLD + tx * 4);
            float4 a4  = *(const float4*)(s_w + 4352 + r * SWLD + tx * 4);
            float4 o;
            o.x = mp4.x * (1.0f - w * e4.x) + w * a4.x;
            o.y = mp4.y * (1.0f - w * e4.y) + w * a4.y;
            o.z = mp4.z * (1.0f - w * e4.z) + w * a4.z;
            o.w = mp4.w * (1.0f - w * e4.w) + w * a4.w;
            *(float4*)(out + (size_t)row * MDIM + c * 64 + tx * 4) = o;
        }
    }
}

extern "C" void kernel_launch(void* const* d_in, const int* in_sizes, int n_in,
                              void* d_out, int out_size) {
    const float* ck   = (const float*)d_in[0];
    const float* qa   = (const float*)d_in[1];
    const float* mk   = (const float*)d_in[2];
    const float* mv   = (const float*)d_in[3];
    const float* We   = (const float*)d_in[4];
    const float* be   = (const float*)d_in[5];
    const float* Wemv = (const float*)d_in[6];
    const float* bemv = (const float*)d_in[7];
    const float* Wza  = (const float*)d_in[8];
    const float* bza  = (const float*)d_in[9];
    const float* Wamv = (const float*)d_in[10];
    const float* bamv = (const float*)d_in[11];
    const float* Wc0  = (const float*)d_in[12];
    const float* bc0  = (const float*)d_in[13];
    const float* Wm1  = (const float*)d_in[14];
    const float* bm1  = (const float*)d_in[15];
    const float* Wz   = (const float*)d_in[16];
    const float* bz   = (const float*)d_in[17];
    const float* Wzmv = (const float*)d_in[18];
    const float* bzmv = (const float*)d_in[19];
    float* out = (float*)d_out;

    const int smem_bytes = SMEM_FLOATS * (int)sizeof(float);  // 103424
    cudaFuncSetAttribute(memnet_fused, cudaFuncAttributeMaxDynamicSharedMemorySize,
                         smem_bytes);

    memnet_fused<<<NROW / 64, 256, smem_bytes>>>(
        ck, qa, mk, mv, We, be, Wemv, bemv, Wza, bza, Wamv, bamv,
        Wc0, bc0, Wm1, bm1, Wz, bz, Wzmv, bzmv, out);
}

// round 6
// speedup vs baseline: 2.9674x; 2.9674x over previous
#include <cuda_runtime.h>
#include <cstdint>

#define NROW 16384      // B
#define MDIM 4096       // M*DV

// 256 MB scratch for memory_pre (fp32, exact output base)
__device__ float g_mpre[(size_t)NROW * MDIM];

__device__ __forceinline__ float sigf(float x) { return 1.0f / (1.0f + __expf(-x)); }
__device__ __forceinline__ float tf32r(float x) {
    float y; asm("cvt.rna.tf32.f32 %0, %1;" : "=f"(y) : "f"(x)); return y;
}

// m16n8k8 tf32 MMA, D accumulates in place.
// A row-major m16xk8: a0=(g,t) a1=(g+8,t) a2=(g,t+4) a3=(g+8,t+4); g=lane>>2, t=lane&3
// B col-major k8xn8:  b0=(t,g) b1=(t+4,g)
// C: c0=(g,2t) c1=(g,2t+1) c2=(g+8,2t) c3=(g+8,2t+1)
__device__ __forceinline__ void mma8(float* c, float a0, float a1, float a2, float a3,
                                     float b0, float b1) {
    asm volatile(
        "mma.sync.aligned.m16n8k8.row.col.f32.tf32.tf32.f32 "
        "{%0,%1,%2,%3}, {%4,%5,%6,%7}, {%8,%9}, {%0,%1,%2,%3};\n"
        : "+f"(c[0]), "+f"(c[1]), "+f"(c[2]), "+f"(c[3])
        : "r"(__float_as_uint(a0)), "r"(__float_as_uint(a1)),
          "r"(__float_as_uint(a2)), "r"(__float_as_uint(a3)),
          "r"(__float_as_uint(b0)), "r"(__float_as_uint(b1)));
}

// Shared memory regions (float offsets). A-operand arrays use LD % 32 == 4,
// B-operand (weight) arrays use LD % 32 == 8 -> conflict-free fragment loads.
#define OFF_A 0                    // 64x132 content0; later reused as [64][68] E/erase
#define OFF_B 8448                 // weights (<=13568 floats); +4608 ck; +8960 logits/ww
#define SZ_B  13568
#define OFF_C (8448 + 13568)       // 22016: [64][68] mv/mp/zt/aA/add (A-operand, LD 68)
#define SMEM_FLOATS (OFF_C + 4352) // 26368 floats = 105472 bytes

__global__ void __launch_bounds__(256, 2)
memnet_tc(const float* __restrict__ ck, const float* __restrict__ qa,
          const float* __restrict__ mk, const float* __restrict__ mv,
          const float* __restrict__ We, const float* __restrict__ be,
          const float* __restrict__ Wemv, const float* __restrict__ bemv,
          const float* __restrict__ Wza, const float* __restrict__ bza,
          const float* __restrict__ Wamv, const float* __restrict__ bamv,
          const float* __restrict__ Wc0, const float* __restrict__ bc0,
          const float* __restrict__ Wm1, const float* __restrict__ bm1,
          const float* __restrict__ Wz, const float* __restrict__ bz,
          const float* __restrict__ Wzmv, const float* __restrict__ bzmv,
          float* __restrict__ out)
{
    extern __shared__ float sm[];
    const int tid = threadIdx.x;
    const int w = tid >> 5;
    const int lane = tid & 31;
    const int g = lane >> 2;         // 0..7
    const int t = lane & 3;          // 0..3
    const int rb = blockIdx.x * 64;

    // warp tilings
    const int wm0 = (w & 1) * 32, wn0 = (w >> 1) * 32;   // phase0: m32 x n32 (out 64x128)
    const int wm1 = (w & 3) * 16, wn1 = (w >> 2) * 32;   // T2: m16 x n32 (out 64x64)
    const int wmE = (w & 1) * 32, wnE = (w >> 1) * 48;   // EZA: m32 x n48 (out 64x192)

    // =================== Phase 0: content0 ===================
    float acc0[2][4][4];
#pragma unroll
    for (int mi = 0; mi < 2; mi++)
#pragma unroll
        for (int j = 0; j < 4; j++)
#pragma unroll
            for (int e = 0; e < 4; e++) acc0[mi][j][e] = 0.0f;

    for (int c = 0; c < 64; c++) {
        __syncthreads();
        // stage mv chunk -> C [64][68] (tf32), Wc0 chunk -> B [64][136] (tf32)
#pragma unroll
        for (int l = 0; l < 4; l++) {
            int idx = tid + l * 256, r = idx >> 4, k4 = idx & 15;
            float4 v = *(const float4*)(mv + (size_t)(rb + r) * MDIM + c * 64 + k4 * 4);
            v.x = tf32r(v.x); v.y = tf32r(v.y); v.z = tf32r(v.z); v.w = tf32r(v.w);
            *(float4*)(sm + OFF_C + r * 68 + k4 * 4) = v;
        }
#pragma unroll
        for (int l = 0; l < 8; l++) {
            int idx = tid + l * 256, k = idx >> 5, n4 = idx & 31;
            float4 v = *(const float4*)(Wc0 + (size_t)(c * 64 + k) * 128 + n4 * 4);
            v.x = tf32r(v.x); v.y = tf32r(v.y); v.z = tf32r(v.z); v.w = tf32r(v.w);
            *(float4*)(sm + OFF_B + k * 136 + n4 * 4) = v;
        }
        __syncthreads();
        const float* A = sm + OFF_C;
        const float* Bw = sm + OFF_B;
#pragma unroll
        for (int k8 = 0; k8 < 8; k8++) {
            int kk = k8 * 8 + t;
            float a[2][4];
#pragma unroll
            for (int mi = 0; mi < 2; mi++) {
                int r = wm0 + mi * 16 + g;
                a[mi][0] = A[r * 68 + kk];
                a[mi][1] = A[(r + 8) * 68 + kk];
                a[mi][2] = A[r * 68 + kk + 4];
                a[mi][3] = A[(r + 8) * 68 + kk + 4];
            }
#pragma unroll
            for (int j = 0; j < 4; j++) {
                float b0 = Bw[kk * 136 + wn0 + j * 8 + g];
                float b1 = Bw[(kk + 4) * 136 + wn0 + j * 8 + g];
                mma8(acc0[0][j], a[0][0], a[0][1], a[0][2], a[0][3], b0, b1);
                mma8(acc0[1][j], a[1][0], a[1][1], a[1][2], a[1][3], b0, b1);
            }
        }
    }
    __syncthreads();
    // content0 epilogue -> s_c0 [64][132], tf32-truncated (GEMM operand only)
#pragma unroll
    for (int mi = 0; mi < 2; mi++)
#pragma unroll
        for (int j = 0; j < 4; j++)
#pragma unroll
            for (int e = 0; e < 2; e++) {
                int col = wn0 + j * 8 + 2 * t + e;
                float bc = bc0[col];
                int r = wm0 + mi * 16 + g;
                float q0 = qa[(size_t)(rb + r) * 128 + col];
                float q1 = qa[(size_t)(rb + r + 8) * 128 + col];
                sm[OFF_A + r * 132 + col]       = tf32r(q0 * sigf(acc0[mi][j][e] + bc));
                sm[OFF_A + (r + 8) * 132 + col] = tf32r(q1 * sigf(acc0[mi][j][2 + e] + bc));
            }

    // =================== Phase 1: gate + memory_pre + EZA reductions ===================
    float aE[2][6][4];
#pragma unroll
    for (int mi = 0; mi < 2; mi++)
#pragma unroll
        for (int j = 0; j < 6; j++)
#pragma unroll
            for (int e = 0; e < 4; e++) aE[mi][j][e] = 0.0f;

    for (int c = 0; c < 64; c++) {
        __syncthreads();
        // stage Wm1 chunk [128][72] (tf32)
#pragma unroll
        for (int l = 0; l < 8; l++) {
            int idx = tid + l * 256, k = idx >> 4, n4 = idx & 15;
            float4 v = *(const float4*)(Wm1 + (size_t)k * MDIM + c * 64 + n4 * 4);
            v.x = tf32r(v.x); v.y = tf32r(v.y); v.z = tf32r(v.z); v.w = tf32r(v.w);
            *(float4*)(sm + OFF_B + k * 72 + n4 * 4) = v;
        }
        __syncthreads();
        // gate GEMM (T2): A = content0 (K=128), B = Wm1 chunk
        float gg[4][4];
#pragma unroll
        for (int j = 0; j < 4; j++)
#pragma unroll
            for (int e = 0; e < 4; e++) gg[j][e] = 0.0f;
        {
            const float* A = sm + OFF_A;
            const float* Bw = sm + OFF_B;
#pragma unroll
            for (int k8 = 0; k8 < 16; k8++) {
                int kk = k8 * 8 + t;
                int r = wm1 + g;
                float a0 = A[r * 132 + kk], a1 = A[(r + 8) * 132 + kk];
                float a2 = A[r * 132 + kk + 4], a3 = A[(r + 8) * 132 + kk + 4];
#pragma unroll
                for (int j = 0; j < 4; j++) {
                    float b0 = Bw[kk * 72 + wn1 + j * 8 + g];
                    float b1 = Bw[(kk + 4) * 72 + wn1 + j * 8 + g];
                    mma8(gg[j], a0, a1, a2, a3, b0, b1);
                }
            }
        }
        // memory_pre (fp32!) -> C
#pragma unroll
        for (int j = 0; j < 4; j++)
#pragma unroll
            for (int e = 0; e < 2; e++) {
                int col = wn1 + j * 8 + 2 * t + e;
                int gcol = c * 64 + col;
                float bm = bm1[gcol];
                int r = wm1 + g;
                float m0 = mv[(size_t)(rb + r) * MDIM + gcol];
                float m1 = mv[(size_t)(rb + r + 8) * MDIM + gcol];
                sm[OFF_C + r * 68 + col]       = m0 * sigf(gg[j][e] + bm);
                sm[OFF_C + (r + 8) * 68 + col] = m1 * sigf(gg[j][2 + e] + bm);
            }
        __syncthreads();
        // copy mp -> g_mpre (coalesced), stage W3 [64][200] (tf32)
#pragma unroll
        for (int l = 0; l < 4; l++) {
            int idx = tid + l * 256, r = idx >> 4, k4 = idx & 15;
            float4 v = *(const float4*)(sm + OFF_C + r * 68 + k4 * 4);
            *(float4*)(g_mpre + (size_t)(rb + r) * MDIM + c * 64 + k4 * 4) = v;
        }
#pragma unroll
        for (int l = 0; l < 4; l++) {
            int idx = tid + l * 256, k = idx >> 4, d4 = idx & 15;
            size_t go = (size_t)(c * 64 + k) * 64 + d4 * 4;
            float4 ve = *(const float4*)(Wemv + go);
            float4 vz = *(const float4*)(Wzmv + go);
            float4 va = *(const float4*)(Wamv + go);
            ve.x = tf32r(ve.x); ve.y = tf32r(ve.y); ve.z = tf32r(ve.z); ve.w = tf32r(ve.w);
            vz.x = tf32r(vz.x); vz.y = tf32r(vz.y); vz.z = tf32r(vz.z); vz.w = tf32r(vz.w);
            va.x = tf32r(va.x); va.y = tf32r(va.y); va.z = tf32r(va.z); va.w = tf32r(va.w);
            *(float4*)(sm + OFF_B + k * 200 + d4 * 4) = ve;
            *(float4*)(sm + OFF_B + k * 200 + 64 + d4 * 4) = vz;
            *(float4*)(sm + OFF_B + k * 200 + 128 + d4 * 4) = va;
        }
        __syncthreads();
        // EZA GEMM: A = mp (fp32, cvt at load), B = [We|Wz|Wa]mv chunk, K=64
        {
            const float* A = sm + OFF_C;
            const float* Bw = sm + OFF_B;
#pragma unroll
            for (int k8 = 0; k8 < 8; k8++) {
                int kk = k8 * 8 + t;
                float a[2][4];
#pragma unroll
                for (int mi = 0; mi < 2; mi++) {
                    int r = wmE + mi * 16 + g;
                    a[mi][0] = tf32r(A[r * 68 + kk]);
                    a[mi][1] = tf32r(A[(r + 8) * 68 + kk]);
                    a[mi][2] = tf32r(A[r * 68 + kk + 4]);
                    a[mi][3] = tf32r(A[(r + 8) * 68 + kk + 4]);
                }
#pragma unroll
                for (int j = 0; j < 6; j++) {
                    float b0 = Bw[kk * 200 + wnE + j * 8 + g];
                    float b1 = Bw[(kk + 4) * 200 + wnE + j * 8 + g];
                    mma8(aE[0][j], a[0][0], a[0][1], a[0][2], a[0][3], b0, b1);
                    mma8(aE[1][j], a[1][0], a[1][1], a[1][2], a[1][3], b0, b1);
                }
            }
        }
    }
    __syncthreads();

    // =================== Epilogue ===================
    // qe = content0 @ We (K=128)
#pragma unroll
    for (int l = 0; l < 8; l++) {
        int idx = tid + l * 256, k = idx >> 4, n4 = idx & 15;
        float4 v = *(const float4*)(We + (size_t)k * 64 + n4 * 4);
        v.x = tf32r(v.x); v.y = tf32r(v.y); v.z = tf32r(v.z); v.w = tf32r(v.w);
        *(float4*)(sm + OFF_B + k * 72 + n4 * 4) = v;
    }
    __syncthreads();
    float qe[4][4];
#pragma unroll
    for (int j = 0; j < 4; j++)
#pragma unroll
        for (int e = 0; e < 4; e++) qe[j][e] = 0.0f;
    {
        const float* A = sm + OFF_A;
        const float* Bw = sm + OFF_B;
#pragma unroll
        for (int k8 = 0; k8 < 16; k8++) {
            int kk = k8 * 8 + t;
            int r = wm1 + g;
            float a0 = A[r * 132 + kk], a1 = A[(r + 8) * 132 + kk];
            float a2 = A[r * 132 + kk + 4], a3 = A[(r + 8) * 132 + kk + 4];
#pragma unroll
            for (int j = 0; j < 4; j++) {
                float b0 = Bw[kk * 72 + wn1 + j * 8 + g];
                float b1 = Bw[(kk + 4) * 72 + wn1 + j * 8 + g];
                mma8(qe[j], a0, a1, a2, a3, b0, b1);
            }
        }
    }
    __syncthreads();
    // qz = content0 @ Wz
#pragma unroll
    for (int l = 0; l < 8; l++) {
        int idx = tid + l * 256, k = idx >> 4, n4 = idx & 15;
        float4 v = *(const float4*)(Wz + (size_t)k * 64 + n4 * 4);
        v.x = tf32r(v.x); v.y = tf32r(v.y); v.z = tf32r(v.z); v.w = tf32r(v.w);
        *(float4*)(sm + OFF_B + k * 72 + n4 * 4) = v;
    }
    __syncthreads();
    float qz[4][4];
#pragma unroll
    for (int j = 0; j < 4; j++)
#pragma unroll
        for (int e = 0; e < 4; e++) qz[j][e] = 0.0f;
    {
        const float* A = sm + OFF_A;
        const float* Bw = sm + OFF_B;
#pragma unroll
        for (int k8 = 0; k8 < 16; k8++) {
            int kk = k8 * 8 + t;
            int r = wm1 + g;
            float a0 = A[r * 132 + kk], a1 = A[(r + 8) * 132 + kk];
            float a2 = A[r * 132 + kk + 4], a3 = A[(r + 8) * 132 + kk + 4];
#pragma unroll
            for (int j = 0; j < 4; j++) {
                float b0 = Bw[kk * 72 + wn1 + j * 8 + g];
                float b1 = Bw[(kk + 4) * 72 + wn1 + j * 8 + g];
                mma8(qz[j], a0, a1, a2, a3, b0, b1);
            }
        }
    }
    __syncthreads();
    // scatter E -> region A [64][68], Z -> region C [64][68]; keep A-part in regs
#pragma unroll
    for (int mi = 0; mi < 2; mi++)
#pragma unroll
        for (int j = 0; j < 6; j++)
#pragma unroll
            for (int ee = 0; ee < 4; ee++) {
                int n = wnE + j * 8 + 2 * t + (ee & 1);
                int r = wmE + mi * 16 + g + ((ee >= 2) ? 8 : 0);
                float v = aE[mi][j][ee];
                if (n < 64)       sm[OFF_A + r * 68 + n] = v;
                else if (n < 128) sm[OFF_C + r * 68 + (n - 64)] = v;
            }
    __syncthreads();
    // erase & zt at T2 positions (in-place rewrite by owner thread)
#pragma unroll
    for (int j = 0; j < 4; j++)
#pragma unroll
        for (int e = 0; e < 2; e++) {
            int col = wn1 + j * 8 + 2 * t + e;
            float bev = be[col], bem = bemv[col];
            float bzv = bz[col], bzm = bzmv[col];
#pragma unroll
            for (int rr = 0; rr < 2; rr++) {
                int r = wm1 + g + rr * 8;
                int ci = rr * 2 + e;
                float E = sm[OFF_A + r * 68 + col];
                float Z = sm[OFF_C + r * 68 + col];
                float er = sigf(sigf(qe[j][ci] + bev) + sigf(E + bem));
                float zt = sigf(qz[j][ci] + bzv + Z + bzm);
                sm[OFF_A + r * 68 + col] = er;
                sm[OFF_C + r * 68 + col] = tf32r(zt);
            }
        }
    __syncthreads();
    // mk^T -> B[0:4608], ck -> B+4608 [64][68] (tf32)
#pragma unroll
    for (int l = 0; l < 4; l++) {
        int idx = tid + l * 256, m = idx >> 4, k4 = idx & 15;
        float4 v = *(const float4*)(mk + (size_t)m * 64 + k4 * 4);
        sm[OFF_B + (k4 * 4 + 0) * 72 + m] = tf32r(v.x);
        sm[OFF_B + (k4 * 4 + 1) * 72 + m] = tf32r(v.y);
        sm[OFF_B + (k4 * 4 + 2) * 72 + m] = tf32r(v.z);
        sm[OFF_B + (k4 * 4 + 3) * 72 + m] = tf32r(v.w);
        float4 c4 = *(const float4*)(ck + (size_t)(rb + m) * 64 + k4 * 4);
        c4.x = tf32r(c4.x); c4.y = tf32r(c4.y); c4.z = tf32r(c4.z); c4.w = tf32r(c4.w);
        *(float4*)(sm + OFF_B + 4608 + m * 68 + k4 * 4) = c4;
    }
    __syncthreads();
    // logits = ck @ mk^T (K=64) -> B+8960 [64][68]
    {
        float lg[4][4];
#pragma unroll
        for (int j = 0; j < 4; j++)
#pragma unroll
            for (int e = 0; e < 4; e++) lg[j][e] = 0.0f;
        const float* A = sm + OFF_B + 4608;
        const float* Bw = sm + OFF_B;
#pragma unroll
        for (int k8 = 0; k8 < 8; k8++) {
            int kk = k8 * 8 + t;
            int r = wm1 + g;
            float a0 = A[r * 68 + kk], a1 = A[(r + 8) * 68 + kk];
            float a2 = A[r * 68 + kk + 4], a3 = A[(r + 8) * 68 + kk + 4];
#pragma unroll
            for (int j = 0; j < 4; j++) {
                float b0 = Bw[kk * 72 + wn1 + j * 8 + g];
                float b1 = Bw[(kk + 4) * 72 + wn1 + j * 8 + g];
                mma8(lg[j], a0, a1, a2, a3, b0, b1);
            }
        }
#pragma unroll
        for (int j = 0; j < 4; j++)
#pragma unroll
            for (int ee = 0; ee < 4; ee++) {
                int col = wn1 + j * 8 + 2 * t + (ee & 1);
                int r = wm1 + g + ((ee >= 2) ? 8 : 0);
                sm[OFF_B + 8960 + r * 68 + col] = lg[j][ee];
            }
    }
    __syncthreads();
    // row softmax over 64 slots -> write weights (in place)
    if (tid < 64) {
        float* row = sm + OFF_B + 8960 + tid * 68;
        float mx = row[0];
        for (int s = 1; s < 64; s++) mx = fmaxf(mx, row[s]);
        float sum = 0.0f;
        for (int s = 0; s < 64; s++) { float e = __expf(row[s] - mx); row[s] = e; sum += e; }
        float inv = 1.0f / sum;
        for (int s = 0; s < 64; s++) row[s] *= inv;
    }
    __syncthreads();
    // Wza -> B[0:4608]
#pragma unroll
    for (int l = 0; l < 4; l++) {
        int idx = tid + l * 256, k = idx >> 4, d4 = idx & 15;
        float4 v = *(const float4*)(Wza + (size_t)k * 64 + d4 * 4);
        v.x = tf32r(v.x); v.y = tf32r(v.y); v.z = tf32r(v.z); v.w = tf32r(v.w);
        *(float4*)(sm + OFF_B + k * 72 + d4 * 4) = v;
    }
    __syncthreads();
    // za = zt @ Wza (K=64)
    float za[4][4];
#pragma unroll
    for (int j = 0; j < 4; j++)
#pragma unroll
        for (int e = 0; e < 4; e++) za[j][e] = 0.0f;
    {
        const float* A = sm + OFF_C;
        const float* Bw = sm + OFF_B;
#pragma unroll
        for (int k8 = 0; k8 < 8; k8++) {
            int kk = k8 * 8 + t;
            int r = wm1 + g;
            float a0 = A[r * 68 + kk], a1 = A[(r + 8) * 68 + kk];
            float a2 = A[r * 68 + kk + 4], a3 = A[(r + 8) * 68 + kk + 4];
#pragma unroll
            for (int j = 0; j < 4; j++) {
                float b0 = Bw[kk * 72 + wn1 + j * 8 + g];
                float b1 = Bw[(kk + 4) * 72 + wn1 + j * 8 + g];
                mma8(za[j], a0, a1, a2, a3, b0, b1);
            }
        }
    }
    __syncthreads();
    // scatter A-part of EZA -> region C (overwrites consumed zt)
#pragma unroll
    for (int mi = 0; mi < 2; mi++)
#pragma unroll
        for (int j = 0; j < 6; j++)
#pragma unroll
            for (int ee = 0; ee < 4; ee++) {
                int n = wnE + j * 8 + 2 * t + (ee & 1);
                if (n >= 128) {
                    int r = wmE + mi * 16 + g + ((ee >= 2) ? 8 : 0);
                    sm[OFF_C + r * 68 + (n - 128)] = aE[mi][j][ee];
                }
            }
    __syncthreads();
    // add signal at T2 positions (in-place)
#pragma unroll
    for (int j = 0; j < 4; j++)
#pragma unroll
        for (int e = 0; e < 2; e++) {
            int col = wn1 + j * 8 + 2 * t + e;
            float bzav = bza[col], bam = bamv[col];
#pragma unroll
            for (int rr = 0; rr < 2; rr++) {
                int r = wm1 + g + rr * 8;
                int ci = rr * 2 + e;
                float Aa = sm[OFF_C + r * 68 + col];
                float ad = tanhf(tanhf(za[j][ci] + bzav) + tanhf(Aa + bam));
                sm[OFF_C + r * 68 + col] = ad;
            }
        }
    __syncthreads();

    // =================== Final pass ===================
    {
        const int tx = tid & 15, ty = tid >> 4;
        for (int c = 0; c < 64; c++) {
#pragma unroll
            for (int i = 0; i < 4; i++) {
                int r = ty * 4 + i;
                int row = rb + r;
                float wv = sm[OFF_B + 8960 + r * 68 + c];
                float4 mp = *(const float4*)(g_mpre + (size_t)row * MDIM + c * 64 + tx * 4);
                float4 e4 = *(const float4*)(sm + OFF_A + r * 68 + tx * 4);
                float4 a4 = *(const float4*)(sm + OFF_C + r * 68 + tx * 4);
                float4 o;
                o.x = mp.x * (1.0f - wv * e4.x) + wv * a4.x;
                o.y = mp.y * (1.0f - wv * e4.y) + wv * a4.y;
                o.z = mp.z * (1.0f - wv * e4.z) + wv * a4.z;
                o.w = mp.w * (1.0f - wv * e4.w) + wv * a4.w;
                *(float4*)(out + (size_t)row * MDIM + c * 64 + tx * 4) = o;
            }
        }
    }
}

extern "C" void kernel_launch(void* const* d_in, const int* in_sizes, int n_in,
                              void* d_out, int out_size) {
    const float* ck   = (const float*)d_in[0];
    const float* qa   = (const float*)d_in[1];
    const float* mk   = (const float*)d_in[2];
    const float* mv   = (const float*)d_in[3];
    const float* We   = (const float*)d_in[4];
    const float* be   = (const float*)d_in[5];
    const float* Wemv = (const float*)d_in[6];
    const float* bemv = (const float*)d_in[7];
    const float* Wza  = (const float*)d_in[8];
    const float* bza  = (const float*)d_in[9];
    const float* Wamv = (const float*)d_in[10];
    const float* bamv = (const float*)d_in[11];
    const float* Wc0  = (const float*)d_in[12];
    const float* bc0  = (const float*)d_in[13];
    const float* Wm1  = (const float*)d_in[14];
    const float* bm1  = (const float*)d_in[15];
    const float* Wz   = (const float*)d_in[16];
    const float* bz   = (const float*)d_in[17];
    const float* Wzmv = (const float*)d_in[18];
    const float* bzmv = (const float*)d_in[19];
    float* out = (float*)d_out;

    const int smem_bytes = SMEM_FLOATS * (int)sizeof(float);  // 105472
    cudaFuncSetAttribute(memnet_tc, cudaFuncAttributeMaxDynamicSharedMemorySize,
                         smem_bytes);
    cudaFuncSetAttribute(memnet_tc, cudaFuncAttributePreferredSharedMemoryCarveout, 100);

    memnet_tc<<<NROW / 64, 256, smem_bytes>>>(
        ck, qa, mk, mv, We, be, Wemv, bemv, Wza, bza, Wamv, bamv,
        Wc0, bc0, Wm1, bm1, Wz, bz, Wzmv, bzmv, out);
}

// round 9
// speedup vs baseline: 3.0883x; 1.0407x over previous
#include <cuda_runtime.h>
#include <cstdint>

#define NROW 16384      // B
#define MDIM 4096       // M*DV

// 256 MB scratch for memory_pre (fp32, exact output base)
__device__ float g_mpre[(size_t)NROW * MDIM];

__device__ __forceinline__ float sigf(float x) { return 1.0f / (1.0f + __expf(-x)); }

// m16n8k8 tf32 MMA, D accumulates in place. Raw fp32 registers are passed;
// the tensor core reads only the tf32 bits (implicit truncation).
// A row-major m16xk8: a0=(g,t) a1=(g+8,t) a2=(g,t+4) a3=(g+8,t+4); g=lane>>2, t=lane&3
// B col-major k8xn8:  b0=(t,g) b1=(t+4,g)
// C: c0=(g,2t) c1=(g,2t+1) c2=(g+8,2t) c3=(g+8,2t+1)
__device__ __forceinline__ void mma8(float* c, float a0, float a1, float a2, float a3,
                                     float b0, float b1) {
    asm volatile(
        "mma.sync.aligned.m16n8k8.row.col.f32.tf32.tf32.f32 "
        "{%0,%1,%2,%3}, {%4,%5,%6,%7}, {%8,%9}, {%0,%1,%2,%3};\n"
        : "+f"(c[0]), "+f"(c[1]), "+f"(c[2]), "+f"(c[3])
        : "r"(__float_as_uint(a0)), "r"(__float_as_uint(a1)),
          "r"(__float_as_uint(a2)), "r"(__float_as_uint(a3)),
          "r"(__float_as_uint(b0)), "r"(__float_as_uint(b1)));
}

// Shared memory regions (float offsets). A-operand arrays use LD % 32 == 4,
// B-operand (weight) arrays use LD % 32 == 8 -> conflict-free fragment loads.
#define OFF_A 0                    // 64x132 content0; later reused as [64][68] E/erase
#define OFF_B 8448                 // weights (<=13568 floats); +4608 ck; +8960 logits/ww
#define SZ_B  13568
#define OFF_C (8448 + 13568)       // 22016: [64][68] mv/mp/zt/aA/add (A-operand, LD 68)
#define SMEM_FLOATS (OFF_C + 4352) // 26368 floats = 105472 bytes

__global__ void __launch_bounds__(256, 2)
memnet_tc(const float* __restrict__ ck, const float* __restrict__ qa,
          const float* __restrict__ mk, const float* __restrict__ mv,
          const float* __restrict__ We, const float* __restrict__ be,
          const float* __restrict__ Wemv, const float* __restrict__ bemv,
          const float* __restrict__ Wza, const float* __restrict__ bza,
          const float* __restrict__ Wamv, const float* __restrict__ bamv,
          const float* __restrict__ Wc0, const float* __restrict__ bc0,
          const float* __restrict__ Wm1, const float* __restrict__ bm1,
          const float* __restrict__ Wz, const float* __restrict__ bz,
          const float* __restrict__ Wzmv, const float* __restrict__ bzmv,
          float* __restrict__ out)
{
    extern __shared__ float sm[];
    const int tid = threadIdx.x;
    const int w = tid >> 5;
    const int lane = tid & 31;
    const int g = lane >> 2;         // 0..7
    const int t = lane & 3;          // 0..3
    const int rb = blockIdx.x * 64;

    // warp tilings
    // phase0: warp grid 2(m) x 2(n) x 2(k-split); each warp m32 x n64, K-half 32
    const int wm0 = (w & 1) * 32, wn0 = ((w >> 1) & 1) * 64, kh0 = (w >> 2) * 32;
    const int wm1 = (w & 3) * 16, wn1 = (w >> 2) * 32;   // T2: m16 x n32 (out 64x64)
    const int wmE = (w & 1) * 32, wnE = (w >> 1) * 48;   // EZA: m32 x n48 (out 64x192)

    // =================== Phase 0: content0 ===================
    float acc0[2][8][4];
#pragma unroll
    for (int mi = 0; mi < 2; mi++)
#pragma unroll
        for (int j = 0; j < 8; j++)
#pragma unroll
            for (int e = 0; e < 4; e++) acc0[mi][j][e] = 0.0f;

#pragma unroll 1
    for (int c = 0; c < 64; c++) {
        __syncthreads();
        // stage mv chunk -> C [64][68] (batched LDG then STS)
        {
            float4 vbuf[4];
#pragma unroll
            for (int l = 0; l < 4; l++) {
                int idx = tid + l * 256, r = idx >> 4, k4 = idx & 15;
                vbuf[l] = *(const float4*)(mv + (size_t)(rb + r) * MDIM + c * 64 + k4 * 4);
            }
#pragma unroll
            for (int l = 0; l < 4; l++) {
                int idx = tid + l * 256, r = idx >> 4, k4 = idx & 15;
                *(float4*)(sm + OFF_C + r * 68 + k4 * 4) = vbuf[l];
            }
        }
        // stage Wc0 chunk -> B [64][136] (two batches of 4)
#pragma unroll
        for (int h = 0; h < 2; h++) {
            float4 wbuf[4];
#pragma unroll
            for (int l = 0; l < 4; l++) {
                int idx = tid + (h * 4 + l) * 256, k = idx >> 5, n4 = idx & 31;
                wbuf[l] = *(const float4*)(Wc0 + (size_t)(c * 64 + k) * 128 + n4 * 4);
            }
#pragma unroll
            for (int l = 0; l < 4; l++) {
                int idx = tid + (h * 4 + l) * 256, k = idx >> 5, n4 = idx & 31;
                *(float4*)(sm + OFF_B + k * 136 + n4 * 4) = wbuf[l];
            }
        }
        __syncthreads();
        const float* A = sm + OFF_C;
        const float* Bw = sm + OFF_B;
#pragma unroll
        for (int k8 = 0; k8 < 4; k8++) {
            int kk = kh0 + k8 * 8 + t;
            float a[2][4];
#pragma unroll
            for (int mi = 0; mi < 2; mi++) {
                int r = wm0 + mi * 16 + g;
                a[mi][0] = A[r * 68 + kk];
                a[mi][1] = A[(r + 8) * 68 + kk];
                a[mi][2] = A[r * 68 + kk + 4];
                a[mi][3] = A[(r + 8) * 68 + kk + 4];
            }
#pragma unroll
            for (int j = 0; j < 8; j++) {
                float b0 = Bw[kk * 136 + wn0 + j * 8 + g];
                float b1 = Bw[(kk + 4) * 136 + wn0 + j * 8 + g];
                mma8(acc0[0][j], a[0][0], a[0][1], a[0][2], a[0][3], b0, b1);
                mma8(acc0[1][j], a[1][0], a[1][1], a[1][2], a[1][3], b0, b1);
            }
        }
    }
    // K-split reduction: warps 4-7 dump partials into OFF_B, warps 0-3 add.
    __syncthreads();
    if (w >= 4) {
#pragma unroll
        for (int mi = 0; mi < 2; mi++)
#pragma unroll
            for (int j = 0; j < 8; j++)
#pragma unroll
                for (int ee = 0; ee < 4; ee++) {
                    int r = wm0 + mi * 16 + g + ((ee >= 2) ? 8 : 0);
                    int col = wn0 + j * 8 + 2 * t + (ee & 1);
                    sm[OFF_B + r * 136 + col] = acc0[mi][j][ee];
                }
    }
    __syncthreads();
    if (w < 4) {
#pragma unroll
        for (int mi = 0; mi < 2; mi++)
#pragma unroll
            for (int j = 0; j < 8; j++)
#pragma unroll
                for (int ee = 0; ee < 4; ee++) {
                    int r = wm0 + mi * 16 + g + ((ee >= 2) ? 8 : 0);
                    int col = wn0 + j * 8 + 2 * t + (ee & 1);
                    acc0[mi][j][ee] += sm[OFF_B + r * 136 + col];
                }
        // content0 epilogue -> s_c0 [64][132] (raw fp32; MMA truncates on use)
#pragma unroll
        for (int mi = 0; mi < 2; mi++)
#pragma unroll
            for (int j = 0; j < 8; j++)
#pragma unroll
                for (int e = 0; e < 2; e++) {
                    int col = wn0 + j * 8 + 2 * t + e;
                    float bc = bc0[col];
                    int r = wm0 + mi * 16 + g;
                    float q0 = qa[(size_t)(rb + r) * 128 + col];
                    float q1 = qa[(size_t)(rb + r + 8) * 128 + col];
                    sm[OFF_A + r * 132 + col]       = q0 * sigf(acc0[mi][j][e] + bc);
                    sm[OFF_A + (r + 8) * 132 + col] = q1 * sigf(acc0[mi][j][2 + e] + bc);
                }
    }

    // =================== Phase 1: gate + memory_pre + EZA reductions ===================
    float aE[2][6][4];
#pragma unroll
    for (int mi = 0; mi < 2; mi++)
#pragma unroll
        for (int j = 0; j < 6; j++)
#pragma unroll
            for (int e = 0; e < 4; e++) aE[mi][j][e] = 0.0f;

#pragma unroll 1
    for (int c = 0; c < 64; c++) {
        __syncthreads();
        // stage Wm1 chunk [128][72] (two batches of 4)
#pragma unroll
        for (int h = 0; h < 2; h++) {
            float4 wbuf[4];
#pragma unroll
            for (int l = 0; l < 4; l++) {
                int idx = tid + (h * 4 + l) * 256, k = idx >> 4, n4 = idx & 15;
                wbuf[l] = *(const float4*)(Wm1 + (size_t)k * MDIM + c * 64 + n4 * 4);
            }
#pragma unroll
            for (int l = 0; l < 4; l++) {
                int idx = tid + (h * 4 + l) * 256, k = idx >> 4, n4 = idx & 15;
                *(float4*)(sm + OFF_B + k * 72 + n4 * 4) = wbuf[l];
            }
        }
        __syncthreads();
        // gate GEMM (T2): A = content0 (K=128), B = Wm1 chunk
        float gg[4][4];
#pragma unroll
        for (int j = 0; j < 4; j++)
#pragma unroll
            for (int e = 0; e < 4; e++) gg[j][e] = 0.0f;
        {
            const float* A = sm + OFF_A;
            const float* Bw = sm + OFF_B;
#pragma unroll
            for (int k8 = 0; k8 < 16; k8++) {
                int kk = k8 * 8 + t;
                int r = wm1 + g;
                float a0 = A[r * 132 + kk], a1 = A[(r + 8) * 132 + kk];
                float a2 = A[r * 132 + kk + 4], a3 = A[(r + 8) * 132 + kk + 4];
#pragma unroll
                for (int j = 0; j < 4; j++) {
                    float b0 = Bw[kk * 72 + wn1 + j * 8 + g];
                    float b1 = Bw[(kk + 4) * 72 + wn1 + j * 8 + g];
                    mma8(gg[j], a0, a1, a2, a3, b0, b1);
                }
            }
        }
        // memory_pre (fp32) -> C
#pragma unroll
        for (int j = 0; j < 4; j++)
#pragma unroll
            for (int e = 0; e < 2; e++) {
                int col = wn1 + j * 8 + 2 * t + e;
                int gcol = c * 64 + col;
                float bm = bm1[gcol];
                int r = wm1 + g;
                float m0 = mv[(size_t)(rb + r) * MDIM + gcol];
                float m1 = mv[(size_t)(rb + r + 8) * MDIM + gcol];
                sm[OFF_C + r * 68 + col]       = m0 * sigf(gg[j][e] + bm);
                sm[OFF_C + (r + 8) * 68 + col] = m1 * sigf(gg[j][2 + e] + bm);
            }
        __syncthreads();
        // copy mp -> g_mpre (coalesced)
        {
            float4 mbuf[4];
#pragma unroll
            for (int l = 0; l < 4; l++) {
                int idx = tid + l * 256, r = idx >> 4, k4 = idx & 15;
                mbuf[l] = *(const float4*)(sm + OFF_C + r * 68 + k4 * 4);
            }
#pragma unroll
            for (int l = 0; l < 4; l++) {
                int idx = tid + l * 256, r = idx >> 4, k4 = idx & 15;
                *(float4*)(g_mpre + (size_t)(rb + r) * MDIM + c * 64 + k4 * 4) = mbuf[l];
            }
        }
        // stage W3 [64][200] (batched: 12 LDG then 12 STS)
        {
            float4 ve[4], vz[4], va[4];
#pragma unroll
            for (int l = 0; l < 4; l++) {
                int idx = tid + l * 256, k = idx >> 4, d4 = idx & 15;
                size_t go = (size_t)(c * 64 + k) * 64 + d4 * 4;
                ve[l] = *(const float4*)(Wemv + go);
                vz[l] = *(const float4*)(Wzmv + go);
                va[l] = *(const float4*)(Wamv + go);
            }
#pragma unroll
            for (int l = 0; l < 4; l++) {
                int idx = tid + l * 256, k = idx >> 4, d4 = idx & 15;
                *(float4*)(sm + OFF_B + k * 200 + d4 * 4)       = ve[l];
                *(float4*)(sm + OFF_B + k * 200 + 64 + d4 * 4)  = vz[l];
                *(float4*)(sm + OFF_B + k * 200 + 128 + d4 * 4) = va[l];
            }
        }
        __syncthreads();
        // EZA GEMM: A = mp (raw fp32), B = [We|Wz|Wa]mv chunk, K=64
        {
            const float* A = sm + OFF_C;
            const float* Bw = sm + OFF_B;
#pragma unroll
            for (int k8 = 0; k8 < 8; k8++) {
                int kk = k8 * 8 + t;
                float a[2][4];
#pragma unroll
                for (int mi = 0; mi < 2; mi++) {
                    int r = wmE + mi * 16 + g;
                    a[mi][0] = A[r * 68 + kk];
                    a[mi][1] = A[(r + 8) * 68 + kk];
                    a[mi][2] = A[r * 68 + kk + 4];
                    a[mi][3] = A[(r + 8) * 68 + kk + 4];
                }
#pragma unroll
                for (int j = 0; j < 6; j++) {
                    float b0 = Bw[kk * 200 + wnE + j * 8 + g];
                    float b1 = Bw[(kk + 4) * 200 + wnE + j * 8 + g];
                    mma8(aE[0][j], a[0][0], a[0][1], a[0][2], a[0][3], b0, b1);
                    mma8(aE[1][j], a[1][0], a[1][1], a[1][2], a[1][3], b0, b1);
                }
            }
        }
    }
    __syncthreads();

    // =================== Epilogue ===================
    // qe = content0 @ We (K=128)
#pragma unroll
    for (int l = 0; l < 8; l++) {
        int idx = tid + l * 256, k = idx >> 4, n4 = idx & 15;
        *(float4*)(sm + OFF_B + k * 72 + n4 * 4) =
            *(const float4*)(We + (size_t)k * 64 + n4 * 4);
    }
    __syncthreads();
    float qe[4][4];
#pragma unroll
    for (int j = 0; j < 4; j++)
#pragma unroll
        for (int e = 0; e < 4; e++) qe[j][e] = 0.0f;
    {
        const float* A = sm + OFF_A;
        const float* Bw = sm + OFF_B;
#pragma unroll
        for (int k8 = 0; k8 < 16; k8++) {
            int kk = k8 * 8 + t;
            int r = wm1 + g;
            float a0 = A[r * 132 + kk], a1 = A[(r + 8) * 132 + kk];
            float a2 = A[r * 132 + kk + 4], a3 = A[(r + 8) * 132 + kk + 4];
#pragma unroll
            for (int j = 0; j < 4; j++) {
                float b0 = Bw[kk * 72 + wn1 + j * 8 + g];
                float b1 = Bw[(kk + 4) * 72 + wn1 + j * 8 + g];
                mma8(qe[j], a0, a1, a2, a3, b0, b1);
            }
        }
    }
    __syncthreads();
    // qz = content0 @ Wz
#pragma unroll
    for (int l = 0; l < 8; l++) {
        int idx = tid + l * 256, k = idx >> 4, n4 = idx & 15;
        *(float4*)(sm + OFF_B + k * 72 + n4 * 4) =
            *(const float4*)(Wz + (size_t)k * 64 + n4 * 4);
    }
    __syncthreads();
    float qz[4][4];
#pragma unroll
    for (int j = 0; j < 4; j++)
#pragma unroll
        for (int e = 0; e < 4; e++) qz[j][e] = 0.0f;
    {
        const float* A = sm + OFF_A;
        const float* Bw = sm + OFF_B;
#pragma unroll
        for (int k8 = 0; k8 < 16; k8++) {
            int kk = k8 * 8 + t;
            int r = wm1 + g;
            float a0 = A[r * 132 + kk], a1 = A[(r + 8) * 132 + kk];
            float a2 = A[r * 132 + kk + 4], a3 = A[(r + 8) * 132 + kk + 4];
#pragma unroll
            for (int j = 0; j < 4; j++) {
                float b0 = Bw[kk * 72 + wn1 + j * 8 + g];
                float b1 = Bw[(kk + 4) * 72 + wn1 + j * 8 + g];
                mma8(qz[j], a0, a1, a2, a3, b0, b1);
            }
        }
    }
    __syncthreads();
    // scatter E -> region A [64][68], Z -> region C [64][68]; keep A-part in regs
#pragma unroll
    for (int mi = 0; mi < 2; mi++)
#pragma unroll
        for (int j = 0; j < 6; j++)
#pragma unroll
            for (int ee = 0; ee < 4; ee++) {
                int n = wnE + j * 8 + 2 * t + (ee & 1);
                int r = wmE + mi * 16 + g + ((ee >= 2) ? 8 : 0);
                float v = aE[mi][j][ee];
                if (n < 64)       sm[OFF_A + r * 68 + n] = v;
                else if (n < 128) sm[OFF_C + r * 68 + (n - 64)] = v;
            }
    __syncthreads();
    // erase & zt at T2 positions (in-place rewrite by owner thread)
#pragma unroll
    for (int j = 0; j < 4; j++)
#pragma unroll
        for (int e = 0; e < 2; e++) {
            int col = wn1 + j * 8 + 2 * t + e;
            float bev = be[col], bem = bemv[col];
            float bzv = bz[col], bzm = bzmv[col];
#pragma unroll
            for (int rr = 0; rr < 2; rr++) {
                int r = wm1 + g + rr * 8;
                int ci = rr * 2 + e;
                float E = sm[OFF_A + r * 68 + col];
                float Z = sm[OFF_C + r * 68 + col];
                float er = sigf(sigf(qe[j][ci] + bev) + sigf(E + bem));
                float zt = sigf(qz[j][ci] + bzv + Z + bzm);
                sm[OFF_A + r * 68 + col] = er;
                sm[OFF_C + r * 68 + col] = zt;
            }
        }
    __syncthreads();
    // mk^T -> B[0:4608], ck -> B+4608 [64][68]
#pragma unroll
    for (int l = 0; l < 4; l++) {
        int idx = tid + l * 256, m = idx >> 4, k4 = idx & 15;
        float4 v = *(const float4*)(mk + (size_t)m * 64 + k4 * 4);
        sm[OFF_B + (k4 * 4 + 0) * 72 + m] = v.x;
        sm[OFF_B + (k4 * 4 + 1) * 72 + m] = v.y;
        sm[OFF_B + (k4 * 4 + 2) * 72 + m] = v.z;
        sm[OFF_B + (k4 * 4 + 3) * 72 + m] = v.w;
        *(float4*)(sm + OFF_B + 4608 + m * 68 + k4 * 4) =
            *(const float4*)(ck + (size_t)(rb + m) * 64 + k4 * 4);
    }
    __syncthreads();
    // logits = ck @ mk^T (K=64) -> B+8960 [64][68]
    {
        float lg[4][4];
#pragma unroll
        for (int j = 0; j < 4; j++)
#pragma unroll
            for (int e = 0; e < 4; e++) lg[j][e] = 0.0f;
        const float* A = sm + OFF_B + 4608;
        const float* Bw = sm + OFF_B;
#pragma unroll
        for (int k8 = 0; k8 < 8; k8++) {
            int kk = k8 * 8 + t;
            int r = wm1 + g;
            float a0 = A[r * 68 + kk], a1 = A[(r + 8) * 68 + kk];
            float a2 = A[r * 68 + kk + 4], a3 = A[(r + 8) * 68 + kk + 4];
#pragma unroll
            for (int j = 0; j < 4; j++) {
                float b0 = Bw[kk * 72 + wn1 + j * 8 + g];
                float b1 = Bw[(kk + 4) * 72 + wn1 + j * 8 + g];
                mma8(lg[j], a0, a1, a2, a3, b0, b1);
            }
        }
#pragma unroll
        for (int j = 0; j < 4; j++)
#pragma unroll
            for (int ee = 0; ee < 4; ee++) {
                int col = wn1 + j * 8 + 2 * t + (ee & 1);
                int r = wm1 + g + ((ee >= 2) ? 8 : 0);
                sm[OFF_B + 8960 + r * 68 + col] = lg[j][ee];
            }
    }
    __syncthreads();
    // row softmax over 64 slots -> write weights (in place)
    if (tid < 64) {
        float* row = sm + OFF_B + 8960 + tid * 68;
        float mx = row[0];
        for (int s = 1; s < 64; s++) mx = fmaxf(mx, row[s]);
        float sum = 0.0f;
        for (int s = 0; s < 64; s++) { float e = __expf(row[s] - mx); row[s] = e; sum += e; }
        float inv = 1.0f / sum;
        for (int s = 0; s < 64; s++) row[s] *= inv;
    }
    __syncthreads();
    // Wza -> B[0:4608]
#pragma unroll
    for (int l = 0; l < 4; l++) {
        int idx = tid + l * 256, k = idx >> 4, d4 = idx & 15;
        *(float4*)(sm + OFF_B + k * 72 + d4 * 4) =
            *(const float4*)(Wza + (size_t)k * 64 + d4 * 4);
    }
    __syncthreads();
    // za = zt @ Wza (K=64)
    float za[4][4];
#pragma unroll
    for (int j = 0; j < 4; j++)
#pragma unroll
        for (int e = 0; e < 4; e++) za[j][e] = 0.0f;
    {
        const float* A = sm + OFF_C;
        const float* Bw = sm + OFF_B;
#pragma unroll
        for (int k8 = 0; k8 < 8; k8++) {
            int kk = k8 * 8 + t;
            int r = wm1 + g;
            float a0 = A[r * 68 + kk], a1 = A[(r + 8) * 68 + kk];
            float a2 = A[r * 68 + kk + 4], a3 = A[(r + 8) * 68 + kk + 4];
#pragma unroll
            for (int j = 0; j < 4; j++) {
                float b0 = Bw[kk * 72 + wn1 + j * 8 + g];
                float b1 = Bw[(kk + 4) * 72 + wn1 + j * 8 + g];
                mma8(za[j], a0, a1, a2, a3, b0, b1);
            }
        }
    }
    __syncthreads();
    // scatter A-part of EZA -> region C (overwrites consumed zt)
#pragma unroll
    for (int mi = 0; mi < 2; mi++)
#pragma unroll
        for (int j = 0; j < 6; j++)
#pragma unroll
            for (int ee = 0; ee < 4; ee++) {
                int n = wnE + j * 8 + 2 * t + (ee & 1);
                if (n >= 128) {
                    int r = wmE + mi * 16 + g + ((ee >= 2) ? 8 : 0);
                    sm[OFF_C + r * 68 + (n - 128)] = aE[mi][j][ee];
                }
            }
    __syncthreads();
    // add signal at T2 positions (in-place)
#pragma unroll
    for (int j = 0; j < 4; j++)
#pragma unroll
        for (int e = 0; e < 2; e++) {
            int col = wn1 + j * 8 + 2 * t + e;
            float bzav = bza[col], bam = bamv[col];
#pragma unroll
            for (int rr = 0; rr < 2; rr++) {
                int r = wm1 + g + rr * 8;
                int ci = rr * 2 + e;
                float Aa = sm[OFF_C + r * 68 + col];
                float ad = tanhf(tanhf(za[j][ci] + bzav) + tanhf(Aa + bam));
                sm[OFF_C + r * 68 + col] = ad;
            }
        }
    __syncthreads();

    // =================== Final pass ===================
    {
        const int tx = tid & 15, ty = tid >> 4;
#pragma unroll 1
        for (int c = 0; c < 64; c++) {
#pragma unroll
            for (int i = 0; i < 4; i++) {
                int r = ty * 4 + i;
                int row = rb + r;
                float wv = sm[OFF_B + 8960 + r * 68 + c];
                float4 mp = *(const float4*)(g_mpre + (size_t)row * MDIM + c * 64 + tx * 4);
                float4 e4 = *(const float4*)(sm + OFF_A + r * 68 + tx * 4);
                float4 a4 = *(const float4*)(sm + OFF_C + r * 68 + tx * 4);
                float4 o;
                o.x = mp.x * (1.0f - wv * e4.x) + wv * a4.x;
                o.y = mp.y * (1.0f - wv * e4.y) + wv * a4.y;
                o.z = mp.z * (1.0f - wv * e4.z) + wv * a4.z;
                o.w = mp.w * (1.0f - wv * e4.w) + wv * a4.w;
                *(float4*)(out + (size_t)row * MDIM + c * 64 + tx * 4) = o;
            }
        }
    }
}

extern "C" void kernel_launch(void* const* d_in, const int* in_sizes, int n_in,
                              void* d_out, int out_size) {
    const float* ck   = (const float*)d_in[0];
    const float* qa   = (const float*)d_in[1];
    const float* mk   = (const float*)d_in[2];
    const float* mv   = (const float*)d_in[3];
    const float* We   = (const float*)d_in[4];
    const float* be   = (const float*)d_in[5];
    const float* Wemv = (const float*)d_in[6];
    const float* bemv = (const float*)d_in[7];
    const float* Wza  = (const float*)d_in[8];
    const float* bza  = (const float*)d_in[9];
    const float* Wamv = (const float*)d_in[10];
    const float* bamv = (const float*)d_in[11];
    const float* Wc0  = (const float*)d_in[12];
    const float* bc0  = (const float*)d_in[13];
    const float* Wm1  = (const float*)d_in[14];
    const float* bm1  = (const float*)d_in[15];
    const float* Wz   = (const float*)d_in[16];
    const float* bz   = (const float*)d_in[17];
    const float* Wzmv = (const float*)d_in[18];
    const float* bzmv = (const float*)d_in[19];
    float* out = (float*)d_out;

    const int smem_bytes = SMEM_FLOATS * (int)sizeof(float);  // 105472
    cudaFuncSetAttribute(memnet_tc, cudaFuncAttributeMaxDynamicSharedMemorySize,
                         smem_bytes);
    cudaFuncSetAttribute(memnet_tc, cudaFuncAttributePreferredSharedMemoryCarveout, 100);

    memnet_tc<<<NROW / 64, 256, smem_bytes>>>(
        ck, qa, mk, mv, We, be, Wemv, bemv, Wza, bza, Wamv, bamv,
        Wc0, bc0, Wm1, bm1, Wz, bz, Wzmv, bzmv, out);
}